// round 1
// baseline (speedup 1.0000x reference)
#include <cuda_runtime.h>

// Problem: B=2048, D=3706
// inputs (metadata order):
//   d_in[0] fake_tensor        float32 [B, D]
//   d_in[1] min_boundary_value float32 [D]
//   d_in[2] interval_lengths   float32 [D, 4]
// output: dist float32 [B, D, 6] followed by val float32 [B, D]
//
// Math (collapsed from reference):
//   b0 = min[d]; b_{k+1} = b_k + relu(len[d,k]) + 1e-4   (strictly increasing)
//   dist[r] = (r==0 || a > b[r-1]) && (r==5 || a < b[r])   (strict: a==b_k -> all zero)
//   val = sum r*dist[r]

#define EPSK 1e-4f

__global__ void __launch_bounds__(256)
discret_kernel(const float* __restrict__ fake,
               const float* __restrict__ minb,
               const float4* __restrict__ lens,
               float* __restrict__ out_dist,   // [B*D*6]
               float* __restrict__ out_val,    // [B*D]
               int total, int D)
{
    int idx = blockIdx.x * blockDim.x + threadIdx.x;
    if (idx >= total) return;

    int d = idx % D;

    float a = fake[idx];
    float4 L = __ldg(&lens[d]);
    float b0 = __ldg(&minb[d]);
    float b1 = b0 + fmaxf(L.x, 0.0f) + EPSK;
    float b2 = b1 + fmaxf(L.y, 0.0f) + EPSK;
    float b3 = b2 + fmaxf(L.z, 0.0f) + EPSK;
    float b4 = b3 + fmaxf(L.w, 0.0f) + EPSK;

    // strict-inequality interval membership (matches heaviside product exactly,
    // including the a==b_k -> all-zeros edge case)
    float d0 = (a < b0)              ? 1.0f : 0.0f;
    float d1 = (a > b0 && a < b1)    ? 1.0f : 0.0f;
    float d2 = (a > b1 && a < b2)    ? 1.0f : 0.0f;
    float d3 = (a > b2 && a < b3)    ? 1.0f : 0.0f;
    float d4 = (a > b3 && a < b4)    ? 1.0f : 0.0f;
    float d5 = (a > b4)              ? 1.0f : 0.0f;

    float val = d1 + 2.0f * d2 + 3.0f * d3 + 4.0f * d4 + 5.0f * d5;

    // 24B per element at byte offset idx*24 -> 8-aligned: three STG.64
    float2* p = reinterpret_cast<float2*>(out_dist + (size_t)idx * 6);
    p[0] = make_float2(d0, d1);
    p[1] = make_float2(d2, d3);
    p[2] = make_float2(d4, d5);

    out_val[idx] = val;
}

extern "C" void kernel_launch(void* const* d_in, const int* in_sizes, int n_in,
                              void* d_out, int out_size)
{
    const float*  fake = (const float*)d_in[0];
    const float*  minb = (const float*)d_in[1];
    const float4* lens = (const float4*)d_in[2];

    int total = in_sizes[0];          // B*D
    int D     = in_sizes[1];          // 3706

    float* out   = (float*)d_out;
    float* dist  = out;                          // [B*D*6]
    float* val   = out + (size_t)total * 6;      // [B*D]

    int threads = 256;
    int blocks  = (total + threads - 1) / threads;
    discret_kernel<<<blocks, threads>>>(fake, minb, lens, dist, val, total, D);
}